// round 11
// baseline (speedup 1.0000x reference)
#include <cuda_runtime.h>
#include <mma.h>

using namespace nvcuda;

#define Hh 512
#define Ww 512
#define Bb 8
#define HW (Hh*Ww)

#define TH 16
#define TW 64
#define NT 512
#define CHUNK 8
#define Y1H (TH+2)   // 18
#define Y1W 66       // conv1 halo cols
#define XH  (TH+4)   // 20
#define XW  72       // padded halo row

// Dynamic smem layout (float offsets)
#define OFF_SX    0
#define SX_F      (3 * XH * XW)            // 4320
#define OFF_SY1T  (OFF_SX + SX_F)          // sy1t[18][66][8] channel-innermost
#define SY1T_F    (Y1H * Y1W * CHUNK)      // 9504
#define OFF_W2S   (OFF_SY1T + SY1T_F)      // w2s[9][8][32] co zero-padded
#define W2S_F     (9 * CHUNK * 32)         // 2304
#define OFF_SW1   (OFF_W2S + W2S_F)
#define SW1_F     (64 * 27)                // 1728
#define OFF_SW1T  (OFF_SW1 + SW1_F)        // [2 sub][27 tap] float4
#define SW1T_F    (2 * 27 * 4)             // 216
#define OFF_SB1   (OFF_SW1T + SW1T_F)      // 64
// epilogue alias region: soff[1024][40] at offset 0
#define SOFF_LD   40
#define SOFF_F    (1024 * SOFF_LD)         // 40960
// persistent constants above the alias region
#define OFF_SB2   40960                    // 18 (+pad)
#define OFF_SWD   40980                    // 81
#define OFF_SBD   41061                    // 3
#define SMEM_F    41064
#define SMEM_BYTES (SMEM_F * 4)            // 164256 B

__global__ __launch_bounds__(NT, 1)
void fused_deform_kernel(const float* __restrict__ x,
                         const float* __restrict__ w1, const float* __restrict__ b1,
                         const float* __restrict__ w2, const float* __restrict__ b2,
                         const float* __restrict__ wd, const float* __restrict__ bd,
                         float* __restrict__ out)
{
    extern __shared__ __align__(16) float SM[];
    float (*sx)[XH][XW] = (float (*)[XH][XW])(SM + OFF_SX);
    float* sy1t = SM + OFF_SY1T;
    float* w2s  = SM + OFF_W2S;
    float* sw1  = SM + OFF_SW1;
    float4* sw1t = (float4*)(SM + OFF_SW1T);
    float* sb1  = SM + OFF_SB1;
    float* sb2  = SM + OFF_SB2;
    float* swd  = SM + OFF_SWD;
    float* sbd  = SM + OFF_SBD;

    const int tid = threadIdx.x;
    const int wrp = tid >> 5;              // 0..15 : owns image row wrp
    const int b   = blockIdx.z;
    const int y0  = blockIdx.y * TH;
    const int x0  = blockIdx.x * TW;

    // ---- stage constants ----
    for (int i = tid; i < 64 * 27; i += NT) sw1[i] = __ldg(&w1[i]);
    if (tid < 64) sb1[tid] = __ldg(&b1[tid]);
    if (tid < 18) sb2[tid] = __ldg(&b2[tid]);
    if (tid < 81) swd[tid] = __ldg(&wd[tid]);
    if (tid < 3)  sbd[tid] = __ldg(&bd[tid]);

    // ---- stage x halo ----
    for (int i = tid; i < SX_F; i += NT) {
        int c  = i / (XH * XW);
        int rr = (i / XW) % XH;
        int cc = i % XW;
        int gy = y0 - 2 + rr;
        int gx = x0 - 2 + cc;
        float v = 0.f;
        if (gy >= 0 && gy < Hh && gx >= 0 && gx < Ww)
            v = __ldg(&x[(size_t)(b * 3 + c) * HW + gy * Ww + gx]);
        sx[c][rr][cc] = v;
    }

    // ---- wmma accumulators: warp wrp -> 4 m-tiles (cols q*16) x 2 n-tiles ----
    wmma::fragment<wmma::accumulator, 16, 16, 8, float> acc[4][2];
#pragma unroll
    for (int q = 0; q < 4; q++) {
        wmma::fill_fragment(acc[q][0], 0.0f);
        wmma::fill_fragment(acc[q][1], 0.0f);
    }

    for (int ch0 = 0; ch0 < 64; ch0 += CHUNK) {
        __syncthreads();  // previous chunk fully consumed

        // stage conv2 weights: w2s[tap][cin][co<32], co>=18 zeroed
        for (int i = tid; i < W2S_F; i += NT) {
            int tap = i >> 8;            // /256
            int cin = (i >> 5) & 7;
            int co  = i & 31;
            w2s[i] = (co < 18) ? __ldg(&w2[co * 576 + (ch0 + cin) * 9 + tap]) : 0.f;
        }
        // stage transposed conv1 weights: sw1t[sub*27+t] = {cl0..cl3}
        if (tid < 216) {
            int sub = tid / 108;
            int rem = tid % 108;
            int t  = rem >> 2;
            int cl = rem & 3;
            ((float*)sw1t)[(sub * 27 + t) * 4 + cl] = sw1[(ch0 + sub * 4 + cl) * 27 + t];
        }
        __syncthreads();

        // conv1 (+ReLU, image-masked): task = 4 channels x 4 px; 612 tasks
        for (int t2 = tid; t2 < 2 * Y1H * 17; t2 += NT) {
            int sub  = t2 / (Y1H * 17);
            int task = t2 % (Y1H * 17);
            int row = task / 17;
            int c0  = (task % 17) * 4;

            float a[4][4];
#pragma unroll
            for (int cl = 0; cl < 4; cl++) {
                float bv = sb1[ch0 + sub * 4 + cl];
                a[cl][0] = bv; a[cl][1] = bv; a[cl][2] = bv; a[cl][3] = bv;
            }
#pragma unroll
            for (int c = 0; c < 3; c++) {
                float v[3][6];
#pragma unroll
                for (int dy = 0; dy < 3; dy++) {
                    float4 p4 = *(const float4*)&sx[c][row + dy][c0];
                    float2 p2 = *(const float2*)&sx[c][row + dy][c0 + 4];
                    v[dy][0] = p4.x; v[dy][1] = p4.y;
                    v[dy][2] = p4.z; v[dy][3] = p4.w;
                    v[dy][4] = p2.x; v[dy][5] = p2.y;
                }
#pragma unroll
                for (int t9 = 0; t9 < 9; t9++) {
                    const int dy = t9 / 3, dx = t9 % 3;
                    float4 w4 = sw1t[sub * 27 + c * 9 + t9];
#pragma unroll
                    for (int j = 0; j < 4; j++) {
                        float vv = v[dy][dx + j];
                        a[0][j] = fmaf(vv, w4.x, a[0][j]);
                        a[1][j] = fmaf(vv, w4.y, a[1][j]);
                        a[2][j] = fmaf(vv, w4.z, a[2][j]);
                        a[3][j] = fmaf(vv, w4.w, a[3][j]);
                    }
                }
            }

            int gyy = y0 - 1 + row;
            bool okY = (gyy >= 0) && (gyy < Hh);
#pragma unroll
            for (int j = 0; j < 4; j++) {
                int col = c0 + j;
                if (col < Y1W) {
                    int gx = x0 - 1 + col;
                    bool ok = okY && (gx >= 0) && (gx < Ww);
                    float* dst = &sy1t[(row * Y1W + col) * CHUNK + sub * 4];
#pragma unroll
                    for (int cl = 0; cl < 4; cl++)
                        dst[cl] = ok ? fmaxf(a[cl][j], 0.f) : 0.f;
                }
            }
        }
        __syncthreads();

        // conv2 via wmma tf32: K-step = 8 cin per tap
#pragma unroll
        for (int t9 = 0; t9 < 9; t9++) {
            const int ky = t9 / 3, kx = t9 % 3;
            wmma::fragment<wmma::matrix_b, 16, 16, 8, wmma::precision::tf32, wmma::row_major> bf[2];
            wmma::load_matrix_sync(bf[0], &w2s[t9 * 256], 32);
            wmma::load_matrix_sync(bf[1], &w2s[t9 * 256 + 16], 32);
#pragma unroll
            for (int e = 0; e < bf[0].num_elements; e++) {
                bf[0].x[e] = wmma::__float_to_tf32(bf[0].x[e]);
                bf[1].x[e] = wmma::__float_to_tf32(bf[1].x[e]);
            }
#pragma unroll
            for (int q = 0; q < 4; q++) {
                wmma::fragment<wmma::matrix_a, 16, 16, 8, wmma::precision::tf32, wmma::row_major> af;
                wmma::load_matrix_sync(af, &sy1t[((wrp + ky) * Y1W + q * 16 + kx) * CHUNK], CHUNK);
#pragma unroll
                for (int e = 0; e < af.num_elements; e++)
                    af.x[e] = wmma::__float_to_tf32(af.x[e]);
                wmma::mma_sync(acc[q][0], af, bf[0], acc[q][0]);
                wmma::mma_sync(acc[q][1], af, bf[1], acc[q][1]);
            }
        }
    }

    // ---- dump offset accumulators to smem (aliases conv scratch) ----
    __syncthreads();
#pragma unroll
    for (int q = 0; q < 4; q++) {
        float* base = SM + (size_t)(wrp * 64 + q * 16) * SOFF_LD;
        wmma::store_matrix_sync(base,      acc[q][0], SOFF_LD, wmma::mem_row_major);
        wmma::store_matrix_sync(base + 16, acc[q][1], SOFF_LD, wmma::mem_row_major);
    }
    __syncthreads();

    // ---- deformable conv epilogue: 2 px per thread ----
    const float* xb = x + (size_t)(b * 3) * HW;
#pragma unroll
    for (int j = 0; j < 2; j++) {
        int px = tid * 2 + j;
        int r  = px >> 6;
        int c  = px & 63;
        int gy = y0 + r;
        int gx = x0 + c;
        const float* op = SM + (size_t)px * SOFF_LD;

        float a0 = sbd[0], a1 = sbd[1], a2 = sbd[2];
#pragma unroll
        for (int k = 0; k < 9; k++) {
            float dy = op[2 * k]     + sb2[2 * k];
            float dx = op[2 * k + 1] + sb2[2 * k + 1];
            float ys = (float)(gy + k / 3 - 1) + dy;
            float xs = (float)(gx + k % 3 - 1) + dx;
            float yf = floorf(ys), xf = floorf(xs);
            int iy0 = (int)yf, ix0 = (int)xf;
            float fy = ys - yf, fx = xs - xf;
            float s0 = 0.f, s1 = 0.f, s2 = 0.f;
#pragma unroll
            for (int cy = 0; cy < 2; cy++)
#pragma unroll
                for (int cx = 0; cx < 2; cx++) {
                    int iy = iy0 + cy, ix = ix0 + cx;
                    float wgt = (cy ? fy : 1.f - fy) * (cx ? fx : 1.f - fx);
                    bool ok = (iy >= 0) && (iy < Hh) && (ix >= 0) && (ix < Ww);
                    wgt = ok ? wgt : 0.f;
                    int idx = min(max(iy, 0), Hh - 1) * Ww + min(max(ix, 0), Ww - 1);
                    s0 = fmaf(wgt, __ldg(xb + idx), s0);
                    s1 = fmaf(wgt, __ldg(xb + HW + idx), s1);
                    s2 = fmaf(wgt, __ldg(xb + 2 * HW + idx), s2);
                }
            a0 = fmaf(s0, swd[ 0 + k], fmaf(s1, swd[ 9 + k], fmaf(s2, swd[18 + k], a0)));
            a1 = fmaf(s0, swd[27 + k], fmaf(s1, swd[36 + k], fmaf(s2, swd[45 + k], a1)));
            a2 = fmaf(s0, swd[54 + k], fmaf(s1, swd[63 + k], fmaf(s2, swd[72 + k], a2)));
        }
        size_t o = (size_t)gy * Ww + gx;
        out[(size_t)(b * 3 + 0) * HW + o] = a0;
        out[(size_t)(b * 3 + 1) * HW + o] = a1;
        out[(size_t)(b * 3 + 2) * HW + o] = a2;
    }
}

extern "C" void kernel_launch(void* const* d_in, const int* in_sizes, int n_in,
                              void* d_out, int out_size)
{
    const float* x  = (const float*)d_in[0];
    const float* w1 = (const float*)d_in[1];
    const float* b1 = (const float*)d_in[2];
    const float* w2 = (const float*)d_in[3];
    const float* b2 = (const float*)d_in[4];
    const float* wd = (const float*)d_in[5];
    const float* bd = (const float*)d_in[6];
    float* out = (float*)d_out;

    cudaFuncSetAttribute(fused_deform_kernel,
                         cudaFuncAttributeMaxDynamicSharedMemorySize, SMEM_BYTES);

    dim3 grid(Ww / TW, Hh / TH, Bb);   // 8 x 32 x 8 = 2048 blocks
    fused_deform_kernel<<<grid, NT, SMEM_BYTES>>>(x, w1, b1, w2, b2, wd, bd, out);
}